// round 8
// baseline (speedup 1.0000x reference)
#include <cuda_runtime.h>
#include <stdint.h>

#define NN 100000
#define DIM 128
#define NE 600000

// Scratch (static device globals; no runtime allocation)
__device__ float g_S0[(size_t)NN * DIM];    // relation-0 feature sums
__device__ float g_S1[(size_t)NN * DIM];    // relation-1 feature sums
__device__ float g_agg[(size_t)NN * DIM];   // post-linear aggregate
__device__ float g_Wt[384 * 128];           // [k][o] tf32 concat of W0|W1|Wself
__device__ float g_Ct[384 * 128];           // [seg*128+c][o] tf32 conv weights
__device__ int   g_idx64;                   // 1 if edge indices are int64
// CSR scratch
__device__ int g_rs0[NN + 1], g_rs1[NN + 1];   // row_start (also histogram)
__device__ int g_cur0[NN], g_cur1[NN];         // fill cursors
__device__ int g_col0[NE], g_col1[NE];         // source node per slot

__device__ __forceinline__ float tf32r(float f) {
    uint32_t u;
    asm("cvt.rna.tf32.f32 %0, %1;" : "=r"(u) : "f"(f));
    return __uint_as_float(u);
}

__device__ __forceinline__ int ld_idx(const void* ei, int i) {
    return g_idx64 ? (int)((const long long*)ei)[i] : ((const int*)ei)[i];
}

// ---------------------------------------------------------------------------
// Zero histograms; block 0 thread 0 detects edge-index dtype
// (int64 node-ids < 2^31 have all odd 32-bit words == 0).
__global__ void zero_cnt_kernel(const int* __restrict__ e0_raw) {
    if (blockIdx.x == 0 && threadIdx.x == 0) {
        int is64 = 1;
        for (int i = 1; i < 64; i += 2)
            if (e0_raw[i] != 0) { is64 = 0; break; }
        g_idx64 = is64;
    }
    int i = blockIdx.x * blockDim.x + threadIdx.x;
    if (i <= NN) { g_rs0[i] = 0; g_rs1[i] = 0; }
}

// Transpose/concat weights once per launch; pre-round to tf32.
__global__ void prep_kernel(const float* __restrict__ W_rel,
                            const float* __restrict__ W_self,
                            const float* __restrict__ conv_w) {
    int t = blockIdx.x * blockDim.x + threadIdx.x;
    if (t >= 384 * 128) return;
    int k = t >> 7, o = t & 127;
    int seg = k >> 7, kl = k & 127;
    float w = (seg < 2) ? W_rel[seg * 16384 + o * 128 + kl]
                        : W_self[o * 128 + kl];
    g_Wt[k * 128 + o] = tf32r(w);
    g_Ct[k * 128 + o] = tf32r(conv_w[o * 384 + kl * 3 + seg]);
}

// Histogram of target nodes (both relations). 4B atomics, spread addresses.
__global__ void hist_kernel(const void* __restrict__ e0,
                            const void* __restrict__ e1) {
    int e = blockIdx.x * blockDim.x + threadIdx.x;
    if (e >= NE) return;
    int s0 = ld_idx(e0, e), t0 = ld_idx(e0, NE + e);
    if ((unsigned)s0 < NN && (unsigned)t0 < NN) atomicAdd(&g_rs0[t0], 1);
    int s1 = ld_idx(e1, e), t1 = ld_idx(e1, NE + e);
    if ((unsigned)s1 < NN && (unsigned)t1 < NN) atomicAdd(&g_rs1[t1], 1);
}

// Exclusive prefix scan over counts -> row_start (+cursor copy), in place.
// grid = 2 (one block per relation), block = 1024.
__global__ void scan_kernel() {
    int* rs  = blockIdx.x ? g_rs1 : g_rs0;
    int* cur = blockIdx.x ? g_cur1 : g_cur0;
    const int CH = (NN + 1023) / 1024;   // 98
    int t = threadIdx.x;
    int begin = t * CH; if (begin > NN) begin = NN;
    int end = begin + CH; if (end > NN) end = NN;
    int sum = 0;
    for (int i = begin; i < end; ++i) sum += rs[i];
    __shared__ int ssum[1024];
    ssum[t] = sum;
    __syncthreads();
    for (int off = 1; off < 1024; off <<= 1) {
        int v = (t >= off) ? ssum[t - off] : 0;
        __syncthreads();
        ssum[t] += v;
        __syncthreads();
    }
    int run = ssum[t] - sum;   // exclusive offset for this chunk
    for (int i = begin; i < end; ++i) {
        int c = rs[i];
        rs[i] = run;
        cur[i] = run;
        run += c;
    }
    if (t == 1023) rs[NN] = ssum[1023];
}

// Fill CSR column (source) arrays.
__global__ void fill_kernel(const void* __restrict__ e0,
                            const void* __restrict__ e1) {
    int e = blockIdx.x * blockDim.x + threadIdx.x;
    if (e >= NE) return;
    int s0 = ld_idx(e0, e), t0 = ld_idx(e0, NE + e);
    if ((unsigned)s0 < NN && (unsigned)t0 < NN)
        g_col0[atomicAdd(&g_cur0[t0], 1)] = s0;
    int s1 = ld_idx(e1, e), t1 = ld_idx(e1, NE + e);
    if ((unsigned)s1 < NN && (unsigned)t1 < NN)
        g_col1[atomicAdd(&g_cur1[t1], 1)] = s1;
}

// Gather: one warp per (node, relation). Sums ~deg source rows of x,
// writes the S row once (no atomics). 2-deep MLP via dual accumulators.
__global__ void gather_kernel(const float* __restrict__ x) {
    int gw = (int)(((size_t)blockIdx.x * blockDim.x + threadIdx.x) >> 5);
    int lane = threadIdx.x & 31;
    if (gw >= 2 * NN) return;
    int rel = (gw >= NN);
    int n = rel ? gw - NN : gw;
    const int* rs  = rel ? g_rs1 : g_rs0;
    const int* col = rel ? g_col1 : g_col0;
    float* S = rel ? g_S1 : g_S0;

    int s = rs[n], e = rs[n + 1];
    float4 a = make_float4(0.f, 0.f, 0.f, 0.f);
    float4 b = make_float4(0.f, 0.f, 0.f, 0.f);
    int j = s;
    for (; j + 1 < e; j += 2) {
        int i1 = col[j], i2 = col[j + 1];
        float4 v1 = ((const float4*)(x + (size_t)i1 * DIM))[lane];
        float4 v2 = ((const float4*)(x + (size_t)i2 * DIM))[lane];
        a.x += v1.x; a.y += v1.y; a.z += v1.z; a.w += v1.w;
        b.x += v2.x; b.y += v2.y; b.z += v2.z; b.w += v2.w;
    }
    if (j < e) {
        int i1 = col[j];
        float4 v1 = ((const float4*)(x + (size_t)i1 * DIM))[lane];
        a.x += v1.x; a.y += v1.y; a.z += v1.z; a.w += v1.w;
    }
    float4 r = make_float4(a.x + b.x, a.y + b.y, a.z + b.z, a.w + b.w);
    ((float4*)(S + (size_t)n * DIM))[lane] = r;
}

// ---------------------------------------------------------------------------
// TF32 tensor-core GEMM, cp.async double-buffered. 128x128 CTA tile,
// 8 warps (4M x 2N) of 32x64, BK=32, mma.sync.m16n8k8.
// MODE 0: g_agg = [S0|S1|x] @ Wcat^T
// MODE 1: out  = relu(conv1d(agg) + b)   (A rows shifted by seg-1)
__device__ __forceinline__ void mma_tf32(float* d, const uint32_t* a,
                                         const uint32_t* b) {
    asm volatile(
        "mma.sync.aligned.m16n8k8.row.col.f32.tf32.tf32.f32 "
        "{%0,%1,%2,%3}, {%4,%5,%6,%7}, {%8,%9}, {%0,%1,%2,%3};"
        : "+f"(d[0]), "+f"(d[1]), "+f"(d[2]), "+f"(d[3])
        : "r"(a[0]), "r"(a[1]), "r"(a[2]), "r"(a[3]), "r"(b[0]), "r"(b[1]));
}

#define AS_STRIDE 36            // floats; 144B row pitch (16B-aligned)
#define BS_STRIDE 136           // floats; 544B row pitch (16B-aligned)
#define ASZ (128 * AS_STRIDE)
#define BSZ (32 * BS_STRIDE)
#define GEMM_SMEM ((2 * (ASZ + BSZ)) * sizeof(float))   // ~71.7 KB

__device__ __forceinline__ void cp16(float* dst, const float* src, bool valid) {
    uint32_t d = (uint32_t)__cvta_generic_to_shared(dst);
    int sz = valid ? 16 : 0;
    asm volatile("cp.async.ca.shared.global [%0], [%1], 16, %2;"
                 :: "r"(d), "l"(src), "r"(sz));
}

template <int MODE>
__global__ __launch_bounds__(256)
void gemm_tf32_kernel(const float* __restrict__ x,
                      const float* __restrict__ conv_b,
                      float* __restrict__ out) {
    extern __shared__ float sm[];
    float* As = sm;                    // [2][ASZ]
    float* Bs = sm + 2 * ASZ;          // [2][BSZ]

    int t = threadIdx.x, lane = t & 31, warp = t >> 5;
    int warpM = warp >> 1, warpN = warp & 1;
    int row0 = blockIdx.x * 128;
    int mrow = lane >> 2, kcol = lane & 3;

    float acc[2][8][4];
#pragma unroll
    for (int mt = 0; mt < 2; mt++)
#pragma unroll
        for (int nt = 0; nt < 8; nt++)
#pragma unroll
            for (int q = 0; q < 4; q++) acc[mt][nt][q] = 0.f;

    auto stage = [&](int kt) {
        int seg = kt >> 2, ko = (kt & 3) * 32;
        const float* Ab;
        int shift;
        if (MODE == 0) {
            Ab = (seg == 0) ? g_S0 : (seg == 1 ? g_S1 : x);
            shift = 0;
        } else {
            Ab = g_agg;
            shift = seg - 1;
        }
        float* Asb = As + (kt & 1) * ASZ;
        float* Bsb = Bs + (kt & 1) * BSZ;
#pragma unroll
        for (int l = 0; l < 4; ++l) {
            int i = l * 256 + t;
            int r = i >> 3, kq = (i & 7) * 4;
            int gr = row0 + r + shift;
            bool valid = (gr >= 0 && gr < NN);
            const float* src = Ab + (size_t)(valid ? gr : 0) * DIM + ko + kq;
            cp16(&Asb[r * AS_STRIDE + kq], src, valid);
        }
        const float* Bsrc = (MODE == 0 ? g_Wt : g_Ct) + kt * 32 * 128;
#pragma unroll
        for (int l = 0; l < 4; ++l) {
            int i = l * 256 + t;
            int k = i >> 5, nq = (i & 31) * 4;
            cp16(&Bsb[k * BS_STRIDE + nq], Bsrc + k * 128 + nq, true);
        }
        asm volatile("cp.async.commit_group;");
    };

    stage(0);
    for (int kt = 0; kt < 12; ++kt) {
        if (kt < 11) {
            stage(kt + 1);
            asm volatile("cp.async.wait_group 1;");
        } else {
            asm volatile("cp.async.wait_group 0;");
        }
        __syncthreads();
        const uint32_t* As_u = (const uint32_t*)(As + (kt & 1) * ASZ);
        const uint32_t* Bs_u = (const uint32_t*)(Bs + (kt & 1) * BSZ);
#pragma unroll
        for (int kk = 0; kk < 4; ++kk) {
            int kb = kk * 8;
            uint32_t afr[2][4], bfr[8][2];
#pragma unroll
            for (int mt = 0; mt < 2; ++mt) {
                int m0 = warpM * 32 + mt * 16 + mrow;
                afr[mt][0] = As_u[m0 * AS_STRIDE + kb + kcol];
                afr[mt][1] = As_u[(m0 + 8) * AS_STRIDE + kb + kcol];
                afr[mt][2] = As_u[m0 * AS_STRIDE + kb + kcol + 4];
                afr[mt][3] = As_u[(m0 + 8) * AS_STRIDE + kb + kcol + 4];
#pragma unroll
                for (int q = 0; q < 4; ++q)
                    afr[mt][q] = __float_as_uint(tf32r(__uint_as_float(afr[mt][q])));
            }
#pragma unroll
            for (int nt = 0; nt < 8; ++nt) {
                int n0 = warpN * 64 + nt * 8 + mrow;
                bfr[nt][0] = Bs_u[(kb + kcol) * BS_STRIDE + n0];
                bfr[nt][1] = Bs_u[(kb + kcol + 4) * BS_STRIDE + n0];
            }
#pragma unroll
            for (int mt = 0; mt < 2; ++mt)
#pragma unroll
                for (int nt = 0; nt < 8; ++nt)
                    mma_tf32(acc[mt][nt], afr[mt], bfr[nt]);
        }
        __syncthreads();
    }

    float* Cout = (MODE == 0) ? g_agg : out;
    int ncol2 = (lane & 3) * 2;
    float2 bias[8];
    if (MODE == 1) {
#pragma unroll
        for (int nt = 0; nt < 8; ++nt) {
            int gc = warpN * 64 + nt * 8 + ncol2;
            bias[nt] = make_float2(__ldg(conv_b + gc), __ldg(conv_b + gc + 1));
        }
    }
#pragma unroll
    for (int mt = 0; mt < 2; ++mt) {
        int rbase = row0 + warpM * 32 + mt * 16 + mrow;
#pragma unroll
        for (int half = 0; half < 2; ++half) {
            int gr = rbase + half * 8;
            if (gr < NN) {
#pragma unroll
                for (int nt = 0; nt < 8; ++nt) {
                    int gc = warpN * 64 + nt * 8 + ncol2;
                    float v0 = acc[mt][nt][half * 2 + 0];
                    float v1 = acc[mt][nt][half * 2 + 1];
                    if (MODE == 1) {
                        v0 = fmaxf(v0 + bias[nt].x, 0.f);
                        v1 = fmaxf(v1 + bias[nt].y, 0.f);
                    }
                    *(float2*)&Cout[(size_t)gr * DIM + gc] = make_float2(v0, v1);
                }
            }
        }
    }
}

// ---------------------------------------------------------------------------
extern "C" void kernel_launch(void* const* d_in, const int* in_sizes, int n_in,
                              void* d_out, int out_size) {
    const float* x      = (const float*)d_in[0];
    const void*  e0     = d_in[1];
    const void*  e1     = d_in[2];
    const float* W_rel  = (const float*)d_in[3];
    const float* W_self = (const float*)d_in[4];
    const float* conv_w = (const float*)d_in[5];
    const float* conv_b = (const float*)d_in[6];
    float* out          = (float*)d_out;

    static bool attr_set = false;
    if (!attr_set) {
        cudaFuncSetAttribute(gemm_tf32_kernel<0>,
                             cudaFuncAttributeMaxDynamicSharedMemorySize, GEMM_SMEM);
        cudaFuncSetAttribute(gemm_tf32_kernel<1>,
                             cudaFuncAttributeMaxDynamicSharedMemorySize, GEMM_SMEM);
        attr_set = true;
    }

    zero_cnt_kernel<<<(NN + 1 + 255) / 256, 256>>>((const int*)e0);
    prep_kernel<<<(384 * 128 + 255) / 256, 256>>>(W_rel, W_self, conv_w);

    // CSR build (counting sort by target) + gather — no feature atomics
    hist_kernel<<<(NE + 255) / 256, 256>>>(e0, e1);
    scan_kernel<<<2, 1024>>>();
    fill_kernel<<<(NE + 255) / 256, 256>>>(e0, e1);
    gather_kernel<<<(2 * NN + 7) / 8, 256>>>(x);

    int gemm_blocks = (NN + 127) / 128;
    gemm_tf32_kernel<0><<<gemm_blocks, 256, GEMM_SMEM>>>(x, conv_b, out);
    gemm_tf32_kernel<1><<<gemm_blocks, 256, GEMM_SMEM>>>(x, conv_b, out);
}

// round 9
// speedup vs baseline: 1.5001x; 1.5001x over previous
#include <cuda_runtime.h>
#include <stdint.h>

#define NN 100000
#define DIM 128
#define NE 600000
#define SCAN_BLOCKS ((NN + 1023) / 1024)   // 98

// Scratch (static device globals; no runtime allocation)
__device__ float g_S0[(size_t)NN * DIM];
__device__ float g_S1[(size_t)NN * DIM];
__device__ float g_agg[(size_t)NN * DIM];
__device__ float g_Wt[384 * 128];           // [k][o] tf32 concat of W0|W1|Wself
__device__ float g_Ct[384 * 128];           // [seg*128+c][o] tf32 conv weights
__device__ int   g_idx64;
// CSR scratch
__device__ __align__(16) int g_rs0[NN + 4], g_rs1[NN + 4];  // row_start / histogram
__device__ int g_cur0[NN], g_cur1[NN];      // fill cursors
__device__ int g_col0[NE], g_col1[NE];      // source node per slot
__device__ int g_bsum[2 * 128];             // per-chunk totals (scan phase 2)

__device__ __forceinline__ float tf32r(float f) {
    uint32_t u;
    asm("cvt.rna.tf32.f32 %0, %1;" : "=r"(u) : "f"(f));
    return __uint_as_float(u);
}

__device__ __forceinline__ int ld_idx(const void* ei, int i) {
    return g_idx64 ? (int)((const long long*)ei)[i] : ((const int*)ei)[i];
}

// ---------------------------------------------------------------------------
// Zero histograms; block 0 thread 0 detects edge-index dtype
// (int64 node-ids < 2^31 have all odd 32-bit words == 0).
__global__ void zero_cnt_kernel(const int* __restrict__ e0_raw) {
    if (blockIdx.x == 0 && threadIdx.x == 0) {
        int is64 = 1;
        for (int i = 1; i < 64; i += 2)
            if (e0_raw[i] != 0) { is64 = 0; break; }
        g_idx64 = is64;
    }
    int i = blockIdx.x * blockDim.x + threadIdx.x;
    if (i <= NN) { g_rs0[i] = 0; g_rs1[i] = 0; }
}

// Transpose/concat weights; pre-round to tf32.
__global__ void prep_kernel(const float* __restrict__ W_rel,
                            const float* __restrict__ W_self,
                            const float* __restrict__ conv_w) {
    int t = blockIdx.x * blockDim.x + threadIdx.x;
    if (t >= 384 * 128) return;
    int k = t >> 7, o = t & 127;
    int seg = k >> 7, kl = k & 127;
    float w = (seg < 2) ? W_rel[seg * 16384 + o * 128 + kl]
                        : W_self[o * 128 + kl];
    g_Wt[k * 128 + o] = tf32r(w);
    g_Ct[k * 128 + o] = tf32r(conv_w[o * 384 + kl * 3 + seg]);
}

// Histogram of target nodes (both relations).
__global__ void hist_kernel(const void* __restrict__ e0,
                            const void* __restrict__ e1) {
    int e = blockIdx.x * blockDim.x + threadIdx.x;
    if (e >= NE) return;
    int s0 = ld_idx(e0, e), t0 = ld_idx(e0, NE + e);
    if ((unsigned)s0 < NN && (unsigned)t0 < NN) atomicAdd(&g_rs0[t0], 1);
    int s1 = ld_idx(e1, e), t1 = ld_idx(e1, NE + e);
    if ((unsigned)s1 < NN && (unsigned)t1 < NN) atomicAdd(&g_rs1[t1], 1);
}

// Scan phase 1: each block exclusive-scans a 1024-count chunk in place,
// emits chunk total. grid = (SCAN_BLOCKS, 2), block = 256.
__global__ void scan1_kernel() {
    int rel = blockIdx.y;
    int* rs = rel ? g_rs1 : g_rs0;
    int t = threadIdx.x;
    int base = blockIdx.x * 1024 + t * 4;
    int4 v = make_int4(0, 0, 0, 0);
    if (base + 3 < NN) v = *(const int4*)(rs + base);
    else {
        if (base + 0 < NN) v.x = rs[base + 0];
        if (base + 1 < NN) v.y = rs[base + 1];
        if (base + 2 < NN) v.z = rs[base + 2];
        if (base + 3 < NN) v.w = rs[base + 3];
    }
    int p1 = v.x, p2 = p1 + v.y, p3 = p2 + v.z;
    int tot = p3 + v.w;
    __shared__ int sh[256];
    sh[t] = tot;
    __syncthreads();
    for (int off = 1; off < 256; off <<= 1) {
        int val = (t >= off) ? sh[t - off] : 0;
        __syncthreads();
        sh[t] += val;
        __syncthreads();
    }
    int excl = sh[t] - tot;
    int4 w = make_int4(excl, excl + p1, excl + p2, excl + p3);
    if (base + 3 < NN) *(int4*)(rs + base) = w;
    else {
        if (base + 0 < NN) rs[base + 0] = w.x;
        if (base + 1 < NN) rs[base + 1] = w.y;
        if (base + 2 < NN) rs[base + 2] = w.z;
        if (base + 3 < NN) rs[base + 3] = w.w;
    }
    if (t == 255) g_bsum[rel * 128 + blockIdx.x] = sh[255];
}

// Scan phase 2: scan the chunk totals. grid = 2, block = 128.
__global__ void scan2_kernel() {
    int rel = blockIdx.x;
    int* rs = rel ? g_rs1 : g_rs0;
    int t = threadIdx.x;
    int v = (t < SCAN_BLOCKS) ? g_bsum[rel * 128 + t] : 0;
    __shared__ int sh[128];
    sh[t] = v;
    __syncthreads();
    for (int off = 1; off < 128; off <<= 1) {
        int val = (t >= off) ? sh[t - off] : 0;
        __syncthreads();
        sh[t] += val;
        __syncthreads();
    }
    g_bsum[rel * 128 + t] = sh[t] - v;   // exclusive chunk offset
    if (t == 127) rs[NN] = sh[127];      // total edge count
}

// Scan phase 3: add chunk offsets, copy cursors. grid = (391, 2), block = 256.
__global__ void scan3_kernel() {
    int rel = blockIdx.y;
    int* rs  = rel ? g_rs1 : g_rs0;
    int* cur = rel ? g_cur1 : g_cur0;
    int i = blockIdx.x * 256 + threadIdx.x;
    if (i < NN) {
        int v = rs[i] + g_bsum[rel * 128 + (i >> 10)];
        rs[i] = v;
        cur[i] = v;
    }
}

// Fill CSR column (source) arrays.
__global__ void fill_kernel(const void* __restrict__ e0,
                            const void* __restrict__ e1) {
    int e = blockIdx.x * blockDim.x + threadIdx.x;
    if (e >= NE) return;
    int s0 = ld_idx(e0, e), t0 = ld_idx(e0, NE + e);
    if ((unsigned)s0 < NN && (unsigned)t0 < NN)
        g_col0[atomicAdd(&g_cur0[t0], 1)] = s0;
    int s1 = ld_idx(e1, e), t1 = ld_idx(e1, NE + e);
    if ((unsigned)s1 < NN && (unsigned)t1 < NN)
        g_col1[atomicAdd(&g_cur1[t1], 1)] = s1;
}

// Gather: one warp per (node, relation); atomic-free row write.
__global__ void gather_kernel(const float* __restrict__ x) {
    int gw = (int)(((size_t)blockIdx.x * blockDim.x + threadIdx.x) >> 5);
    int lane = threadIdx.x & 31;
    if (gw >= 2 * NN) return;
    int rel = (gw >= NN);
    int n = rel ? gw - NN : gw;
    const int* rs  = rel ? g_rs1 : g_rs0;
    const int* col = rel ? g_col1 : g_col0;
    float* S = rel ? g_S1 : g_S0;

    int s = rs[n], e = rs[n + 1];
    float4 a = make_float4(0.f, 0.f, 0.f, 0.f);
    float4 b = make_float4(0.f, 0.f, 0.f, 0.f);
    int j = s;
    for (; j + 1 < e; j += 2) {
        int i1 = col[j], i2 = col[j + 1];
        float4 v1 = ((const float4*)(x + (size_t)i1 * DIM))[lane];
        float4 v2 = ((const float4*)(x + (size_t)i2 * DIM))[lane];
        a.x += v1.x; a.y += v1.y; a.z += v1.z; a.w += v1.w;
        b.x += v2.x; b.y += v2.y; b.z += v2.z; b.w += v2.w;
    }
    if (j < e) {
        int i1 = col[j];
        float4 v1 = ((const float4*)(x + (size_t)i1 * DIM))[lane];
        a.x += v1.x; a.y += v1.y; a.z += v1.z; a.w += v1.w;
    }
    float4 r = make_float4(a.x + b.x, a.y + b.y, a.z + b.z, a.w + b.w);
    ((float4*)(S + (size_t)n * DIM))[lane] = r;
}

// ---------------------------------------------------------------------------
// TF32 tensor-core GEMM, cp.async double-buffered. 128x128 CTA tile,
// 8 warps (4M x 2N), BK=32, mma.sync.m16n8k8.
// MODE 0: g_agg = [S0|S1|x] @ Wcat^T
// MODE 1: out  = relu(conv1d(agg) + b)   (A rows shifted by seg-1)
__device__ __forceinline__ void mma_tf32(float* d, const uint32_t* a,
                                         const uint32_t* b) {
    asm volatile(
        "mma.sync.aligned.m16n8k8.row.col.f32.tf32.tf32.f32 "
        "{%0,%1,%2,%3}, {%4,%5,%6,%7}, {%8,%9}, {%0,%1,%2,%3};"
        : "+f"(d[0]), "+f"(d[1]), "+f"(d[2]), "+f"(d[3])
        : "r"(a[0]), "r"(a[1]), "r"(a[2]), "r"(a[3]), "r"(b[0]), "r"(b[1]));
}

#define AS_STRIDE 36
#define BS_STRIDE 136
#define ASZ (128 * AS_STRIDE)
#define BSZ (32 * BS_STRIDE)
#define GEMM_SMEM ((2 * (ASZ + BSZ)) * sizeof(float))   // ~71.7 KB

__device__ __forceinline__ void cp16(float* dst, const float* src, bool valid) {
    uint32_t d = (uint32_t)__cvta_generic_to_shared(dst);
    int sz = valid ? 16 : 0;
    asm volatile("cp.async.ca.shared.global [%0], [%1], 16, %2;"
                 :: "r"(d), "l"(src), "r"(sz));
}

template <int MODE>
__global__ __launch_bounds__(256)
void gemm_tf32_kernel(const float* __restrict__ x,
                      const float* __restrict__ conv_b,
                      float* __restrict__ out) {
    extern __shared__ float sm[];
    float* As = sm;
    float* Bs = sm + 2 * ASZ;

    int t = threadIdx.x, lane = t & 31, warp = t >> 5;
    int warpM = warp >> 1, warpN = warp & 1;
    int row0 = blockIdx.x * 128;
    int mrow = lane >> 2, kcol = lane & 3;

    float acc[2][8][4];
#pragma unroll
    for (int mt = 0; mt < 2; mt++)
#pragma unroll
        for (int nt = 0; nt < 8; nt++)
#pragma unroll
            for (int q = 0; q < 4; q++) acc[mt][nt][q] = 0.f;

    auto stage = [&](int kt) {
        int seg = kt >> 2, ko = (kt & 3) * 32;
        const float* Ab;
        int shift;
        if (MODE == 0) {
            Ab = (seg == 0) ? g_S0 : (seg == 1 ? g_S1 : x);
            shift = 0;
        } else {
            Ab = g_agg;
            shift = seg - 1;
        }
        float* Asb = As + (kt & 1) * ASZ;
        float* Bsb = Bs + (kt & 1) * BSZ;
#pragma unroll
        for (int l = 0; l < 4; ++l) {
            int i = l * 256 + t;
            int r = i >> 3, kq = (i & 7) * 4;
            int gr = row0 + r + shift;
            bool valid = (gr >= 0 && gr < NN);
            const float* src = Ab + (size_t)(valid ? gr : 0) * DIM + ko + kq;
            cp16(&Asb[r * AS_STRIDE + kq], src, valid);
        }
        const float* Bsrc = (MODE == 0 ? g_Wt : g_Ct) + kt * 32 * 128;
#pragma unroll
        for (int l = 0; l < 4; ++l) {
            int i = l * 256 + t;
            int k = i >> 5, nq = (i & 31) * 4;
            cp16(&Bsb[k * BS_STRIDE + nq], Bsrc + k * 128 + nq, true);
        }
        asm volatile("cp.async.commit_group;");
    };

    stage(0);
    for (int kt = 0; kt < 12; ++kt) {
        if (kt < 11) {
            stage(kt + 1);
            asm volatile("cp.async.wait_group 1;");
        } else {
            asm volatile("cp.async.wait_group 0;");
        }
        __syncthreads();
        const uint32_t* As_u = (const uint32_t*)(As + (kt & 1) * ASZ);
        const uint32_t* Bs_u = (const uint32_t*)(Bs + (kt & 1) * BSZ);
#pragma unroll
        for (int kk = 0; kk < 4; ++kk) {
            int kb = kk * 8;
            uint32_t afr[2][4], bfr[8][2];
#pragma unroll
            for (int mt = 0; mt < 2; ++mt) {
                int m0 = warpM * 32 + mt * 16 + mrow;
                afr[mt][0] = As_u[m0 * AS_STRIDE + kb + kcol];
                afr[mt][1] = As_u[(m0 + 8) * AS_STRIDE + kb + kcol];
                afr[mt][2] = As_u[m0 * AS_STRIDE + kb + kcol + 4];
                afr[mt][3] = As_u[(m0 + 8) * AS_STRIDE + kb + kcol + 4];
#pragma unroll
                for (int q = 0; q < 4; ++q)
                    afr[mt][q] = __float_as_uint(tf32r(__uint_as_float(afr[mt][q])));
            }
#pragma unroll
            for (int nt = 0; nt < 8; ++nt) {
                int n0 = warpN * 64 + nt * 8 + mrow;
                bfr[nt][0] = Bs_u[(kb + kcol) * BS_STRIDE + n0];
                bfr[nt][1] = Bs_u[(kb + kcol + 4) * BS_STRIDE + n0];
            }
#pragma unroll
            for (int mt = 0; mt < 2; ++mt)
#pragma unroll
                for (int nt = 0; nt < 8; ++nt)
                    mma_tf32(acc[mt][nt], afr[mt], bfr[nt]);
        }
        __syncthreads();
    }

    float* Cout = (MODE == 0) ? g_agg : out;
    int ncol2 = (lane & 3) * 2;
    float2 bias[8];
    if (MODE == 1) {
#pragma unroll
        for (int nt = 0; nt < 8; ++nt) {
            int gc = warpN * 64 + nt * 8 + ncol2;
            bias[nt] = make_float2(__ldg(conv_b + gc), __ldg(conv_b + gc + 1));
        }
    }
#pragma unroll
    for (int mt = 0; mt < 2; ++mt) {
        int rbase = row0 + warpM * 32 + mt * 16 + mrow;
#pragma unroll
        for (int half = 0; half < 2; ++half) {
            int gr = rbase + half * 8;
            if (gr < NN) {
#pragma unroll
                for (int nt = 0; nt < 8; ++nt) {
                    int gc = warpN * 64 + nt * 8 + ncol2;
                    float v0 = acc[mt][nt][half * 2 + 0];
                    float v1 = acc[mt][nt][half * 2 + 1];
                    if (MODE == 1) {
                        v0 = fmaxf(v0 + bias[nt].x, 0.f);
                        v1 = fmaxf(v1 + bias[nt].y, 0.f);
                    }
                    *(float2*)&Cout[(size_t)gr * DIM + gc] = make_float2(v0, v1);
                }
            }
        }
    }
}

// ---------------------------------------------------------------------------
extern "C" void kernel_launch(void* const* d_in, const int* in_sizes, int n_in,
                              void* d_out, int out_size) {
    const float* x      = (const float*)d_in[0];
    const void*  e0     = d_in[1];
    const void*  e1     = d_in[2];
    const float* W_rel  = (const float*)d_in[3];
    const float* W_self = (const float*)d_in[4];
    const float* conv_w = (const float*)d_in[5];
    const float* conv_b = (const float*)d_in[6];
    float* out          = (float*)d_out;

    static bool attr_set = false;
    if (!attr_set) {
        cudaFuncSetAttribute(gemm_tf32_kernel<0>,
                             cudaFuncAttributeMaxDynamicSharedMemorySize, GEMM_SMEM);
        cudaFuncSetAttribute(gemm_tf32_kernel<1>,
                             cudaFuncAttributeMaxDynamicSharedMemorySize, GEMM_SMEM);
        attr_set = true;
    }

    zero_cnt_kernel<<<(NN + 1 + 255) / 256, 256>>>((const int*)e0);
    prep_kernel<<<(384 * 128 + 255) / 256, 256>>>(W_rel, W_self, conv_w);

    // CSR build (counting sort by target) + gather — no feature atomics
    hist_kernel<<<(NE + 255) / 256, 256>>>(e0, e1);
    scan1_kernel<<<dim3(SCAN_BLOCKS, 2), 256>>>();
    scan2_kernel<<<2, 128>>>();
    scan3_kernel<<<dim3((NN + 255) / 256, 2), 256>>>();
    fill_kernel<<<(NE + 255) / 256, 256>>>(e0, e1);
    gather_kernel<<<(2 * NN + 7) / 8, 256>>>(x);

    int gemm_blocks = (NN + 127) / 128;
    gemm_tf32_kernel<0><<<gemm_blocks, 256, GEMM_SMEM>>>(x, conv_b, out);
    gemm_tf32_kernel<1><<<gemm_blocks, 256, GEMM_SMEM>>>(x, conv_b, out);
}